// round 16
// baseline (speedup 1.0000x reference)
#include <cuda_runtime.h>
#include <cuda_fp16.h>
#include <math.h>
#include <stdint.h>

#define SEQ 8192
#define DM 1024
#define NH 16
#define DH 64
#define NN (NH*DH)   // 1024

#define KTOT 1024
#define KSTAGE 128                 // halves per panel (two 128B sub-panels)
#define NSTG 2
#define NKT (KTOT/KSTAGE)          // 8 panels
#define A_SUB 32768                // 256 rows x 128B per sub-panel
#define B_SUB 16384                // 128 rows x 128B per sub-panel
#define A_BYTES (2*A_SUB)          // 65536
#define B_BYTES (2*B_SUB)          // 32768
#define STG_BYTES (A_BYTES + B_BYTES)   // 98304
#define SMEM_BYTES (NSTG*STG_BYTES)     // 196608

#define NC 128                     // scan chunks
#define CH 64                      // steps per chunk

// ---------------- scratch ----------------
__device__ __half g_xs_h[SEQ * DM];
__device__ __half g_wk_h[NN * DM];
__device__ __half g_wv_h[NN * DM];
__device__ __half g_w1_h[DM * NN];
__device__ __half g_w2_h[NN * DM];
__device__ __half g_attn_h[SEQ * NN];
__device__ __half g_h1_h[SEQ * DM];
__device__ __half g_v_h[SEQ * NN];   // v projection, fp16
__device__ float g_aT  [NH * SEQ];   // act-sum, head-major
__device__ float g_pa  [NC * NH];
__device__ float g_pav [NC * NN];
__device__ float g_bav [NC * NN];
__device__ float g_basea[NC * NH];

__device__ __forceinline__ uint32_t smem_u32(const void* p) {
    uint32_t a;
    asm("{ .reg .u64 t; cvta.to.shared.u64 t, %1; cvt.u32.u64 %0, t; }" : "=r"(a) : "l"(p));
    return a;
}

// one stage: A = 8 x 16B, B = 4 x 16B cp.async per thread (512 threads, 96KB)
__device__ __forceinline__ void load_stage(uint32_t sb, int s, int kt,
                                           const __half* gA, const __half* gB,
                                           const uint32_t* doffA, const uint32_t* doffB)
{
    const uint32_t ab = sb + s * STG_BYTES;
    const uint32_t bb = ab + A_BYTES;
    const __half* a = gA + kt * KSTAGE;
    const __half* b = gB + kt * KSTAGE;
#pragma unroll
    for (int i = 0; i < 8; i++)
        asm volatile("cp.async.cg.shared.global [%0], [%1], 16;"
                     :: "r"(ab + doffA[i]), "l"(a + i * 8) : "memory");
#pragma unroll
    for (int i = 0; i < 4; i++)
        asm volatile("cp.async.cg.shared.global [%0], [%1], 16;"
                     :: "r"(bb + doffB[i]), "l"(b + i * 8) : "memory");
    asm volatile("cp.async.commit_group;" ::: "memory");
}

// ---------------------------------------------------------------------------
// GEMM core: 256x128 CTA tile, 16 warps (4x4) of 64x32, 2-stage x 96KB
// double buffer (8 K-panels of 128). Inner kg loop identical to the R11-proven
// pattern; sub-panel select adds only a compile-time base offset.
// ---------------------------------------------------------------------------
__device__ __forceinline__ void gemm_core(const __half* __restrict__ A,
                                          const __half* __restrict__ B,
                                          int bm, int bn, float* smf,
                                          float (&acc)[4][4][4])
{
    const uint32_t sb = smem_u32(smf);
    const int tid = threadIdx.x, lane = tid & 31, wid = tid >> 5;
    const int warp_m = (wid >> 2) * 64;
    const int warp_n = (wid & 3) * 32;

    // A staging: row tid>>1, half-panel ha=tid&1 (k halves [64ha,64ha+64))
    const int arow = tid >> 1;
    const int ha = tid & 1;
    const __half* gA = A + (size_t)(bm * 256 + arow) * KTOT + ha * 64;
    uint32_t doffA[8];
#pragma unroll
    for (int i = 0; i < 8; i++)
        doffA[i] = ha * A_SUB + arow * 128 + (((i) ^ (arow & 7)) << 4);

    // B staging: row tid>>2, quarter qb=tid&3 (chunks qb*4..qb*4+3)
    const int brow = tid >> 2;
    const int qb = tid & 3;
    const __half* gB = B + (size_t)(bn * 128 + brow) * KTOT + qb * 32;
    uint32_t doffB[4];
#pragma unroll
    for (int i = 0; i < 4; i++) {
        int c = qb * 4 + i;                 // chunk 0..15
        doffB[i] = (c >> 3) * B_SUB + brow * 128 + (((c & 7) ^ (brow & 7)) << 4);
    }

    const int rbase = (lane & 7) + ((lane >> 3) & 1) * 8;
    const int klane = lane >> 4;
    const int rA_base = warp_m + rbase;
    const int rB_base = warp_n + rbase;

#pragma unroll
    for (int i = 0; i < 4; i++)
#pragma unroll
        for (int j = 0; j < 4; j++)
#pragma unroll
            for (int q = 0; q < 4; q++) acc[i][j][q] = 0.f;

    load_stage(sb, 0, 0, gA, gB, doffA, doffB);

    for (int kt = 0; kt < NKT; kt++) {
        asm volatile("cp.async.wait_group 0;" ::: "memory");
        __syncthreads();
        if (kt + 1 < NKT) load_stage(sb, (kt + 1) & 1, kt + 1, gA, gB, doffA, doffB);

        const uint32_t stg = sb + (kt & 1) * STG_BYTES;

#pragma unroll
        for (int kg = 0; kg < 8; kg++) {
            const uint32_t ab = stg + (kg >> 2) * A_SUB;
            const uint32_t bb = stg + A_BYTES + (kg >> 2) * B_SUB;
            const int kc = 2 * (kg & 3) + klane;
            uint32_t bfr[8];
#pragma unroll
            for (int p = 0; p < 2; p++) {
                const int row = rB_base + 16 * p;
                uint32_t addr = bb + (uint32_t)row * 128 + (uint32_t)((kc ^ (row & 7)) << 4);
                asm volatile("ldmatrix.sync.aligned.m8n8.x4.shared.b16 {%0,%1,%2,%3}, [%4];"
                    : "=r"(bfr[4*p]), "=r"(bfr[4*p+1]), "=r"(bfr[4*p+2]), "=r"(bfr[4*p+3])
                    : "r"(addr));
            }
#pragma unroll
            for (int i = 0; i < 4; i++) {
                const int row = rA_base + 16 * i;
                uint32_t af[4];
                uint32_t addr = ab + (uint32_t)row * 128 + (uint32_t)((kc ^ (row & 7)) << 4);
                asm volatile("ldmatrix.sync.aligned.m8n8.x4.shared.b16 {%0,%1,%2,%3}, [%4];"
                    : "=r"(af[0]), "=r"(af[1]), "=r"(af[2]), "=r"(af[3]) : "r"(addr));
#pragma unroll
                for (int j = 0; j < 4; j++) {
                    const int bi = (j >> 1) * 4 + (j & 1);
                    asm volatile(
                        "mma.sync.aligned.m16n8k16.row.col.f32.f16.f16.f32 "
                        "{%0,%1,%2,%3}, {%4,%5,%6,%7}, {%8,%9}, {%0,%1,%2,%3};"
                        : "+f"(acc[i][j][0]), "+f"(acc[i][j][1]),
                          "+f"(acc[i][j][2]), "+f"(acc[i][j][3])
                        : "r"(af[0]), "r"(af[1]), "r"(af[2]), "r"(af[3]),
                          "r"(bfr[bi]), "r"(bfr[bi + 2]));
                }
            }
        }
    }
}

// ---------------------------------------------------------------------------
// Fused K+V projection: grid (16, 32). bx<8 -> k-proj; bx>=8 -> v-proj.
// ---------------------------------------------------------------------------
__global__ __launch_bounds__(512, 1)
void gemm_kv(const __half* __restrict__ xs, const __half* __restrict__ wk,
             const __half* __restrict__ wv)
{
    extern __shared__ float smf[];
    const int bm = blockIdx.y;
    const bool is_k = blockIdx.x < 8;
    const int bn = blockIdx.x & 7;

    float acc[4][4][4];
    gemm_core(xs, is_k ? wk : wv, bm, bn, smf, acc);

    const int tid = threadIdx.x, lane = tid & 31, wid = tid >> 5;
    const int warp_m = (wid >> 2) * 64;
    const int warp_n = (wid & 3) * 32;
    const int g = lane >> 2, tig = lane & 3;

    if (is_k) {
        // red lives in stage 0 (last panel kt=7 computed from stage 1; the
        // kt=7 sync guarantees every warp finished the stage-0 compute).
        float* red = smf;   // [256 rows][4 warp_n groups]
#pragma unroll
        for (int i = 0; i < 4; i++) {
#pragma unroll
            for (int half = 0; half < 2; half++) {
                float s = 0.f;
#pragma unroll
                for (int j = 0; j < 4; j++) {
                    float x0 = acc[i][j][2 * half + 0];
                    float x1 = acc[i][j][2 * half + 1];
                    s += (x0 > 0.f) ? (x0 + 1.f) : expf(x0);
                    s += (x1 > 0.f) ? (x1 + 1.f) : expf(x1);
                }
                s += __shfl_xor_sync(0xFFFFFFFFu, s, 1);
                s += __shfl_xor_sync(0xFFFFFFFFu, s, 2);
                if (tig == 0)
                    red[(warp_m + 16 * i + 8 * half + g) * 4 + (wid & 3)] = s;
            }
        }
        __syncthreads();
        {
            const int row = tid >> 1, hsel = tid & 1;
            float s = red[row * 4 + 2 * hsel] + red[row * 4 + 2 * hsel + 1];
            g_aT[(size_t)(bn * 2 + hsel) * SEQ + bm * 256 + row] = s;
        }
    } else {
#pragma unroll
        for (int i = 0; i < 4; i++) {
            int row0 = bm * 256 + warp_m + 16 * i + g;
#pragma unroll
            for (int j = 0; j < 4; j++) {
                int colg = bn * 128 + warp_n + 8 * j + 2 * tig;
#pragma unroll
                for (int half = 0; half < 2; half++) {
                    int row = row0 + 8 * half;
                    __half2 o = __floats2half2_rn(acc[i][j][2 * half], acc[i][j][2 * half + 1]);
                    *(__half2*)(g_v_h + (size_t)row * 1024 + colg) = o;
                }
            }
        }
    }
}

// ---------------------------------------------------------------------------
// MLP GEMMs: grid (8, 32). EPI: 2 = gelu(x+b)->fp16, 3 = x+b->f32
// ---------------------------------------------------------------------------
template<int EPI>
__global__ __launch_bounds__(512, 1)
void gemm_h(const __half* __restrict__ A, const __half* __restrict__ B,
            const float* __restrict__ bias, void* __restrict__ Cv)
{
    extern __shared__ float smf[];
    const int bm = blockIdx.y, bn = blockIdx.x;

    float acc[4][4][4];
    gemm_core(A, B, bm, bn, smf, acc);

    const int tid = threadIdx.x, lane = tid & 31, wid = tid >> 5;
    const int warp_m = (wid >> 2) * 64;
    const int warp_n = (wid & 3) * 32;
    const int g = lane >> 2, tig = lane & 3;

#pragma unroll
    for (int i = 0; i < 4; i++) {
        int row0 = bm * 256 + warp_m + 16 * i + g;
#pragma unroll
        for (int j = 0; j < 4; j++) {
            int colg = bn * 128 + warp_n + 8 * j + 2 * tig;
            float bia0 = bias[colg], bia1 = bias[colg + 1];
#pragma unroll
            for (int half = 0; half < 2; half++) {
                int row = row0 + 8 * half;
                float x0 = acc[i][j][2 * half + 0] + bia0;
                float x1 = acc[i][j][2 * half + 1] + bia1;
                if (EPI == 2) {
                    float t0 = 0.7978845608028654f * (x0 + 0.044715f * x0 * x0 * x0);
                    float t1 = 0.7978845608028654f * (x1 + 0.044715f * x1 * x1 * x1);
                    x0 = 0.5f * x0 * (1.f + tanhf(t0));
                    x1 = 0.5f * x1 * (1.f + tanhf(t1));
                    __half2 o = __floats2half2_rn(x0, x1);
                    *(__half2*)((__half*)Cv + (size_t)row * 1024 + colg) = o;
                } else {
                    float2 o = make_float2(x0, x1);
                    *(float2*)((float*)Cv + (size_t)row * 1024 + colg) = o;
                }
            }
        }
    }
}

// ---------------------------------------------------------------------------
// f32 -> fp16 conversion: one launch for xs (8 segs) + 4 weights (1 seg each).
__global__ void conv_all(const float4* __restrict__ xs, __half2* __restrict__ xs_h,
                         const float4* __restrict__ s0, __half2* __restrict__ d0,
                         const float4* __restrict__ s1, __half2* __restrict__ d1,
                         const float4* __restrict__ s2, __half2* __restrict__ d2,
                         const float4* __restrict__ s3, __half2* __restrict__ d3)
{
    const int SEG = 262144;
    const int stride = gridDim.x * blockDim.x;
    int i = blockIdx.x * blockDim.x + threadIdx.x;
#pragma unroll
    for (int k = 0; k < 4; k++) {
        int idx = i + k * stride;
        if (idx >= 12 * SEG) continue;
        const float4* s; __half2* d; int off;
        if (idx < 8 * SEG) { s = xs; d = xs_h; off = idx; }
        else {
            int seg = (idx >> 18) - 8;
            off = idx & (SEG - 1);
            if (seg == 0) { s = s0; d = d0; }
            else if (seg == 1) { s = s1; d = d1; }
            else if (seg == 2) { s = s2; d = d2; }
            else { s = s3; d = d3; }
        }
        float4 v = s[off];
        d[2 * off]     = __floats2half2_rn(v.x, v.y);
        d[2 * off + 1] = __floats2half2_rn(v.z, v.w);
    }
}

// ---- chunked scans: NC=128 chunks of CH=64 steps ----
__global__ void scan_pass1()
{
    const int c = blockIdx.x, h = blockIdx.y, v = threadIdx.x;   // v: 0..31
    __shared__ float a_s[CH];
    const float* ap = g_aT + (size_t)h * SEQ + c * CH;
    a_s[v]      = ap[v];
    a_s[v + 32] = ap[v + 32];
    __syncwarp();

    float s = a_s[v] + a_s[v + 32];
#pragma unroll
    for (int off = 16; off > 0; off >>= 1)
        s += __shfl_xor_sync(0xFFFFFFFFu, s, off);
    if (v == 0) g_pa[c * NH + h] = s;

    const __half2* vp = (const __half2*)(g_v_h + (size_t)c * CH * NN + h * DH) + v;
    float ax0 = 0.f, ay0 = 0.f, ax1 = 0.f, ay1 = 0.f;
#pragma unroll
    for (int t = 0; t < CH; t += 2) {
        float2 p0 = __half22float2(vp[(size_t)t * (NN / 2)]);
        float2 p1 = __half22float2(vp[(size_t)(t + 1) * (NN / 2)]);
        ax0 = fmaf(a_s[t], p0.x, ax0);
        ay0 = fmaf(a_s[t], p0.y, ay0);
        ax1 = fmaf(a_s[t + 1], p1.x, ax1);
        ay1 = fmaf(a_s[t + 1], p1.y, ay1);
    }
    const int hv = h * DH + 2 * v;
    float2 o = make_float2(ax0 + ax1, ay0 + ay1);
    *(float2*)(g_pav + c * NN + hv) = o;
}

// pass2c (R14-proven): 32 blocks x 256 threads; warp w owns chunks
// [16w,16w+16), lane = hv offset -> every global access is a full 128B line.
__global__ void scan_pass2c()
{
    const int lane = threadIdx.x & 31, w = threadIdx.x >> 5;
    const int hv = blockIdx.x * 32 + lane;
    __shared__ float part[8][32];
    __shared__ float part2[8][16];

    float vals[16];
    float run = 0.f;
#pragma unroll
    for (int i = 0; i < 16; i++) {
        float x = g_pav[(w * 16 + i) * NN + hv];
        vals[i] = run;
        run += x;
    }
    part[w][lane] = run;

    const bool do2 = (blockIdx.x == 0 && lane < NH);
    float vals2[16];
    float run2 = 0.f;
    if (do2) {
#pragma unroll
        for (int i = 0; i < 16; i++) {
            float x = g_pa[(w * 16 + i) * NH + lane];
            vals2[i] = run2;
            run2 += x;
        }
        part2[w][lane] = run2;
    }
    __syncthreads();

    float off = 0.f, off2 = 0.f;
#pragma unroll
    for (int k = 0; k < 8; k++) {
        if (k < w) {
            off += part[k][lane];
            if (do2) off2 += part2[k][lane];
        }
    }
#pragma unroll
    for (int i = 0; i < 16; i++)
        g_bav[(w * 16 + i) * NN + hv] = off + vals[i];
    if (do2) {
#pragma unroll
        for (int i = 0; i < 16; i++)
            g_basea[(w * 16 + i) * NH + lane] = off2 + vals2[i];
    }
}

// pass3: 32 threads/block, shfl pair-scan of a, __half2 v/attn access.
__global__ void scan_pass3()
{
    const int c = blockIdx.x, h = blockIdx.y, v = threadIdx.x;   // 0..31
    __shared__ float a_s[CH];
    __shared__ float inv_s[CH];
    const float* ap = g_aT + (size_t)h * SEQ + c * CH;
    a_s[v]      = ap[v];
    a_s[v + 32] = ap[v + 32];
    __syncwarp();

    float a0 = a_s[2 * v], a1 = a_s[2 * v + 1];
    float p = a0 + a1, sp = p;
#pragma unroll
    for (int off = 1; off < 32; off <<= 1) {
        float n = __shfl_up_sync(0xFFFFFFFFu, sp, off);
        if (v >= off) sp += n;
    }
    float base = g_basea[c * NH + h];
    float excl = base + sp - p;
    inv_s[2 * v]     = 1.0f / (excl + a0);
    inv_s[2 * v + 1] = 1.0f / (excl + a0 + a1);
    __syncwarp();

    const int hv = h * DH + 2 * v;
    const __half2* vp = (const __half2*)(g_v_h + (size_t)c * CH * NN + h * DH) + v;
    __half2* op = (__half2*)(g_attn_h + (size_t)c * CH * NN + h * DH) + v;
    float2 bacc = *(const float2*)(g_bav + c * NN + hv);
    float accx = bacc.x;
    float accy = bacc.y;
#pragma unroll 4
    for (int t = 0; t < CH; t++) {
        float2 pv = __half22float2(vp[(size_t)t * (NN / 2)]);
        accx = fmaf(a_s[t], pv.x, accx);
        accy = fmaf(a_s[t], pv.y, accy);
        float inv = inv_s[t];
        op[(size_t)t * (NN / 2)] = __floats2half2_rn(accx * inv, accy * inv);
    }
}

// ---------------------------------------------------------------------------
extern "C" void kernel_launch(void* const* d_in, const int* in_sizes, int n_in,
                              void* d_out, int out_size)
{
    const float* xs = (const float*)d_in[0];
    // d_in[1] = wq: unused (query factor cancels in sq/zq)
    const float* wk = (const float*)d_in[2];
    const float* wv = (const float*)d_in[3];
    const float* w1 = (const float*)d_in[4];
    const float* b1 = (const float*)d_in[5];
    const float* w2 = (const float*)d_in[6];
    const float* b2 = (const float*)d_in[7];
    float* out = (float*)d_out;

    __half *xs_h, *wk_h, *wv_h, *w1_h, *w2_h, *attn_h, *h1_h;
    cudaGetSymbolAddress((void**)&xs_h, g_xs_h);
    cudaGetSymbolAddress((void**)&wk_h, g_wk_h);
    cudaGetSymbolAddress((void**)&wv_h, g_wv_h);
    cudaGetSymbolAddress((void**)&w1_h, g_w1_h);
    cudaGetSymbolAddress((void**)&w2_h, g_w2_h);
    cudaGetSymbolAddress((void**)&attn_h, g_attn_h);
    cudaGetSymbolAddress((void**)&h1_h, g_h1_h);

    cudaFuncSetAttribute(gemm_kv,   cudaFuncAttributeMaxDynamicSharedMemorySize, SMEM_BYTES);
    cudaFuncSetAttribute(gemm_h<2>, cudaFuncAttributeMaxDynamicSharedMemorySize, SMEM_BYTES);
    cudaFuncSetAttribute(gemm_h<3>, cudaFuncAttributeMaxDynamicSharedMemorySize, SMEM_BYTES);

    // 1: conversions (one launch)
    conv_all<<<(12 * 262144) / (256 * 4), 256>>>(
        (const float4*)xs, (__half2*)xs_h,
        (const float4*)wk, (__half2*)wk_h, (const float4*)wv, (__half2*)wv_h,
        (const float4*)w1, (__half2*)w1_h, (const float4*)w2, (__half2*)w2_h);

    // 2: fused k+v projection
    gemm_kv<<<dim3(16, 32), 512, SMEM_BYTES>>>(xs_h, wk_h, wv_h);

    // 3-5: linear-attention chunked scan
    scan_pass1<<<dim3(NC, NH), 32>>>();
    scan_pass2c<<<NN / 32, 256>>>();
    scan_pass3<<<dim3(NC, NH), 32>>>();

    // 6-7: MLP
    gemm_h<2><<<dim3(8, 32), 512, SMEM_BYTES>>>(attn_h, w1_h, b1, h1_h);
    gemm_h<3><<<dim3(8, 32), 512, SMEM_BYTES>>>(h1_h, w2_h, b2, out);
}

// round 17
// speedup vs baseline: 1.2398x; 1.2398x over previous
#include <cuda_runtime.h>
#include <cuda_fp16.h>
#include <math.h>
#include <stdint.h>

#define SEQ 8192
#define DM 1024
#define NH 16
#define DH 64
#define NN (NH*DH)   // 1024

#define KTOT 1024
#define KSTAGE 64                  // halves per panel row (128B)
#define NSTG 3
#define NKT (KTOT/KSTAGE)          // 16 panels
#define A_BYTES 32768              // 256 rows x 128B
#define B_BYTES 16384              // 128 rows x 128B
#define STG_BYTES (A_BYTES + B_BYTES)   // 49152
#define SMEM_BYTES (NSTG*STG_BYTES)     // 147456

#define NC 128                     // scan chunks
#define CH 64                      // steps per chunk

// ---------------- scratch ----------------
__device__ __half g_xs_h[SEQ * DM];
__device__ __half g_wk_h[NN * DM];
__device__ __half g_wv_h[NN * DM];
__device__ __half g_w1_h[DM * NN];
__device__ __half g_w2_h[NN * DM];
__device__ __half g_attn_h[SEQ * NN];
__device__ __half g_h1_h[SEQ * DM];
__device__ __half g_v_h[SEQ * NN];   // v projection, fp16
__device__ float g_a   [SEQ * NH];
__device__ float g_pa  [NC * NH];    // per-chunk sums of a
__device__ float g_pav [NC * NN];    // per-chunk sums of a*v
__device__ float g_bav [NC * NN];    // exclusive chunk bases of a*v
__device__ float g_basea[NC * NH];   // exclusive chunk bases of a

__device__ __forceinline__ uint32_t smem_u32(const void* p) {
    uint32_t a;
    asm("{ .reg .u64 t; cvta.to.shared.u64 t, %1; cvt.u32.u64 %0, t; }" : "=r"(a) : "l"(p));
    return a;
}

// one stage: A = 4 x 16B, B = 2 x 16B cp.async per thread (512 threads, 48KB)
__device__ __forceinline__ void load_stage(uint32_t sb, int s, int kt,
                                           const __half* gA, const __half* gB,
                                           const uint32_t* doffA, const uint32_t* doffB)
{
    const uint32_t ab = sb + s * STG_BYTES;
    const uint32_t bb = ab + A_BYTES;
    const __half* a = gA + kt * KSTAGE;
    const __half* b = gB + kt * KSTAGE;
#pragma unroll
    for (int i = 0; i < 4; i++)
        asm volatile("cp.async.cg.shared.global [%0], [%1], 16;"
                     :: "r"(ab + doffA[i]), "l"(a + i * 8) : "memory");
#pragma unroll
    for (int i = 0; i < 2; i++)
        asm volatile("cp.async.cg.shared.global [%0], [%1], 16;"
                     :: "r"(bb + doffB[i]), "l"(b + i * 8) : "memory");
    asm volatile("cp.async.commit_group;" ::: "memory");
}

// ---------------------------------------------------------------------------
// GEMM core (R11/R14-proven, DO NOT MODIFY): 256x128 CTA tile, 16 warps (4x4)
// of 64x32, cp.async 3-stage, ldmatrix, m16n8k16 fp16 -> f32.
// ---------------------------------------------------------------------------
__device__ __forceinline__ void gemm_core(const __half* __restrict__ A,
                                          const __half* __restrict__ B,
                                          int bm, int bn, float* smf,
                                          float (&acc)[4][4][4])
{
    const uint32_t sb = smem_u32(smf);
    const int tid = threadIdx.x, lane = tid & 31, wid = tid >> 5;
    const int warp_m = (wid >> 2) * 64;
    const int warp_n = (wid & 3) * 32;

    const int arow = tid >> 1;
    const int ac0 = (tid & 1) * 4;
    const __half* gA = A + (size_t)(bm * 256 + arow) * KTOT + ac0 * 8;
    uint32_t doffA[4];
#pragma unroll
    for (int i = 0; i < 4; i++)
        doffA[i] = arow * 128 + (((ac0 + i) ^ (arow & 7)) << 4);

    const int brow = tid >> 2;
    const int bc0 = (tid & 3) * 2;
    const __half* gB = B + (size_t)(bn * 128 + brow) * KTOT + bc0 * 8;
    uint32_t doffB[2];
#pragma unroll
    for (int i = 0; i < 2; i++)
        doffB[i] = brow * 128 + (((bc0 + i) ^ (brow & 7)) << 4);

    const int rbase = (lane & 7) + ((lane >> 3) & 1) * 8;
    const int klane = lane >> 4;
    const int rA_base = warp_m + rbase;
    const int rB_base = warp_n + rbase;

#pragma unroll
    for (int i = 0; i < 4; i++)
#pragma unroll
        for (int j = 0; j < 4; j++)
#pragma unroll
            for (int q = 0; q < 4; q++) acc[i][j][q] = 0.f;

    load_stage(sb, 0, 0, gA, gB, doffA, doffB);
    load_stage(sb, 1, 1, gA, gB, doffA, doffB);

    for (int kt = 0; kt < NKT; kt++) {
        if (kt + 1 < NKT) asm volatile("cp.async.wait_group 1;" ::: "memory");
        else              asm volatile("cp.async.wait_group 0;" ::: "memory");
        __syncthreads();
        if (kt + 2 < NKT) load_stage(sb, (kt + 2) % NSTG, kt + 2, gA, gB, doffA, doffB);

        const uint32_t ab = sb + (kt % NSTG) * STG_BYTES;
        const uint32_t bb = ab + A_BYTES;

#pragma unroll
        for (int kg = 0; kg < 4; kg++) {
            const int kc = 2 * kg + klane;
            uint32_t bfr[8];
#pragma unroll
            for (int p = 0; p < 2; p++) {
                const int row = rB_base + 16 * p;
                uint32_t addr = bb + (uint32_t)row * 128 + (uint32_t)((kc ^ (row & 7)) << 4);
                asm volatile("ldmatrix.sync.aligned.m8n8.x4.shared.b16 {%0,%1,%2,%3}, [%4];"
                    : "=r"(bfr[4*p]), "=r"(bfr[4*p+1]), "=r"(bfr[4*p+2]), "=r"(bfr[4*p+3])
                    : "r"(addr));
            }
#pragma unroll
            for (int i = 0; i < 4; i++) {
                const int row = rA_base + 16 * i;
                uint32_t af[4];
                uint32_t addr = ab + (uint32_t)row * 128 + (uint32_t)((kc ^ (row & 7)) << 4);
                asm volatile("ldmatrix.sync.aligned.m8n8.x4.shared.b16 {%0,%1,%2,%3}, [%4];"
                    : "=r"(af[0]), "=r"(af[1]), "=r"(af[2]), "=r"(af[3]) : "r"(addr));
#pragma unroll
                for (int j = 0; j < 4; j++) {
                    const int bi = (j >> 1) * 4 + (j & 1);
                    asm volatile(
                        "mma.sync.aligned.m16n8k16.row.col.f32.f16.f16.f32 "
                        "{%0,%1,%2,%3}, {%4,%5,%6,%7}, {%8,%9}, {%0,%1,%2,%3};"
                        : "+f"(acc[i][j][0]), "+f"(acc[i][j][1]),
                          "+f"(acc[i][j][2]), "+f"(acc[i][j][3])
                        : "r"(af[0]), "r"(af[1]), "r"(af[2]), "r"(af[3]),
                          "r"(bfr[bi]), "r"(bfr[bi + 2]));
                }
            }
        }
    }
}

// ---------------------------------------------------------------------------
// Fused K+V projection: grid (16, 32). bx<8 -> k-proj; bx>=8 -> v-proj.
// ---------------------------------------------------------------------------
__global__ __launch_bounds__(512, 1)
void gemm_kv(const __half* __restrict__ xs, const __half* __restrict__ wk,
             const __half* __restrict__ wv)
{
    extern __shared__ float smf[];
    const int bm = blockIdx.y;
    const bool is_k = blockIdx.x < 8;
    const int bn = blockIdx.x & 7;

    float acc[4][4][4];
    gemm_core(xs, is_k ? wk : wv, bm, bn, smf, acc);

    const int tid = threadIdx.x, lane = tid & 31, wid = tid >> 5;
    const int warp_m = (wid >> 2) * 64;
    const int warp_n = (wid & 3) * 32;
    const int g = lane >> 2, tig = lane & 3;

    if (is_k) {
        float* red = smf + (STG_BYTES / 4);   // [256 rows][4 warp_n groups]
#pragma unroll
        for (int i = 0; i < 4; i++) {
#pragma unroll
            for (int half = 0; half < 2; half++) {
                float s = 0.f;
#pragma unroll
                for (int j = 0; j < 4; j++) {
                    float x0 = acc[i][j][2 * half + 0];
                    float x1 = acc[i][j][2 * half + 1];
                    s += (x0 > 0.f) ? (x0 + 1.f) : expf(x0);
                    s += (x1 > 0.f) ? (x1 + 1.f) : expf(x1);
                }
                s += __shfl_xor_sync(0xFFFFFFFFu, s, 1);
                s += __shfl_xor_sync(0xFFFFFFFFu, s, 2);
                if (tig == 0)
                    red[(warp_m + 16 * i + 8 * half + g) * 4 + (wid & 3)] = s;
            }
        }
        __syncthreads();
        {
            const int row = tid >> 1, hsel = tid & 1;
            float s = red[row * 4 + 2 * hsel] + red[row * 4 + 2 * hsel + 1];
            g_a[(size_t)(bm * 256 + row) * NH + bn * 2 + hsel] = s;
        }
    } else {
#pragma unroll
        for (int i = 0; i < 4; i++) {
            int row0 = bm * 256 + warp_m + 16 * i + g;
#pragma unroll
            for (int j = 0; j < 4; j++) {
                int colg = bn * 128 + warp_n + 8 * j + 2 * tig;
#pragma unroll
                for (int half = 0; half < 2; half++) {
                    int row = row0 + 8 * half;
                    __half2 o = __floats2half2_rn(acc[i][j][2 * half], acc[i][j][2 * half + 1]);
                    *(__half2*)(g_v_h + (size_t)row * 1024 + colg) = o;
                }
            }
        }
    }
}

// ---------------------------------------------------------------------------
// MLP GEMMs: grid (8, 32). EPI: 2 = gelu(x+b)->fp16, 3 = x+b->f32
// ---------------------------------------------------------------------------
template<int EPI>
__global__ __launch_bounds__(512, 1)
void gemm_h(const __half* __restrict__ A, const __half* __restrict__ B,
            const float* __restrict__ bias, void* __restrict__ Cv)
{
    extern __shared__ float smf[];
    const int bm = blockIdx.y, bn = blockIdx.x;

    float acc[4][4][4];
    gemm_core(A, B, bm, bn, smf, acc);

    const int tid = threadIdx.x, lane = tid & 31, wid = tid >> 5;
    const int warp_m = (wid >> 2) * 64;
    const int warp_n = (wid & 3) * 32;
    const int g = lane >> 2, tig = lane & 3;

#pragma unroll
    for (int i = 0; i < 4; i++) {
        int row0 = bm * 256 + warp_m + 16 * i + g;
#pragma unroll
        for (int j = 0; j < 4; j++) {
            int colg = bn * 128 + warp_n + 8 * j + 2 * tig;
            float bia0 = bias[colg], bia1 = bias[colg + 1];
#pragma unroll
            for (int half = 0; half < 2; half++) {
                int row = row0 + 8 * half;
                float x0 = acc[i][j][2 * half + 0] + bia0;
                float x1 = acc[i][j][2 * half + 1] + bia1;
                if (EPI == 2) {
                    float t0 = 0.7978845608028654f * (x0 + 0.044715f * x0 * x0 * x0);
                    float t1 = 0.7978845608028654f * (x1 + 0.044715f * x1 * x1 * x1);
                    x0 = 0.5f * x0 * (1.f + tanhf(t0));
                    x1 = 0.5f * x1 * (1.f + tanhf(t1));
                    __half2 o = __floats2half2_rn(x0, x1);
                    *(__half2*)((__half*)Cv + (size_t)row * 1024 + colg) = o;
                } else {
                    float2 o = make_float2(x0, x1);
                    *(float2*)((float*)Cv + (size_t)row * 1024 + colg) = o;
                }
            }
        }
    }
}

// ---------------------------------------------------------------------------
// f32 -> fp16 conversion: one launch for xs (8 segs) + 4 weights (1 seg each).
__global__ void conv_all(const float4* __restrict__ xs, __half2* __restrict__ xs_h,
                         const float4* __restrict__ s0, __half2* __restrict__ d0,
                         const float4* __restrict__ s1, __half2* __restrict__ d1,
                         const float4* __restrict__ s2, __half2* __restrict__ d2,
                         const float4* __restrict__ s3, __half2* __restrict__ d3)
{
    const int SEG = 262144;               // float4s per 1M-float tensor
    const int stride = gridDim.x * blockDim.x;
    int i = blockIdx.x * blockDim.x + threadIdx.x;
#pragma unroll
    for (int k = 0; k < 4; k++) {
        int idx = i + k * stride;
        if (idx >= 12 * SEG) continue;
        const float4* s; __half2* d; int off;
        if (idx < 8 * SEG) { s = xs; d = xs_h; off = idx; }
        else {
            int seg = (idx >> 18) - 8;
            off = idx & (SEG - 1);
            if (seg == 0) { s = s0; d = d0; }
            else if (seg == 1) { s = s1; d = d1; }
            else if (seg == 2) { s = s2; d = d2; }
            else { s = s3; d = d3; }
        }
        float4 v = s[off];
        d[2 * off]     = __floats2half2_rn(v.x, v.y);
        d[2 * off + 1] = __floats2half2_rn(v.z, v.w);
    }
}

// ---- chunked scans: NC=128 chunks of CH=64 steps ----
// pass1: 32 threads/block, thread covers 2 hv via __half2.
__global__ void scan_pass1()
{
    const int c = blockIdx.x, h = blockIdx.y, v = threadIdx.x;   // v: 0..31
    __shared__ float a_s[CH];
    a_s[v]      = g_a[(c * CH + v) * NH + h];
    a_s[v + 32] = g_a[(c * CH + v + 32) * NH + h];
    __syncwarp();

    float s = a_s[v] + a_s[v + 32];
#pragma unroll
    for (int off = 16; off > 0; off >>= 1)
        s += __shfl_xor_sync(0xFFFFFFFFu, s, off);
    if (v == 0) g_pa[c * NH + h] = s;

    const __half2* vp = (const __half2*)(g_v_h + (size_t)c * CH * NN + h * DH) + v;
    float ax0 = 0.f, ay0 = 0.f, ax1 = 0.f, ay1 = 0.f;
#pragma unroll
    for (int t = 0; t < CH; t += 2) {
        float2 p0 = __half22float2(vp[(size_t)t * (NN / 2)]);
        float2 p1 = __half22float2(vp[(size_t)(t + 1) * (NN / 2)]);
        ax0 = fmaf(a_s[t], p0.x, ax0);
        ay0 = fmaf(a_s[t], p0.y, ay0);
        ax1 = fmaf(a_s[t + 1], p1.x, ax1);
        ay1 = fmaf(a_s[t + 1], p1.y, ay1);
    }
    const int hv = h * DH + 2 * v;
    g_pav[c * NN + hv]     = ax0 + ax1;
    g_pav[c * NN + hv + 1] = ay0 + ay1;
}

// pass2c: coalesced chunk scans. 32 blocks x 256 threads; warp w owns chunks
// [16w,16w+16), lane = hv offset -> every global access is a full 128B line.
__global__ void scan_pass2c()
{
    const int lane = threadIdx.x & 31, w = threadIdx.x >> 5;
    const int hv = blockIdx.x * 32 + lane;
    __shared__ float part[8][32];
    __shared__ float part2[8][16];

    float vals[16];
    float run = 0.f;
#pragma unroll
    for (int i = 0; i < 16; i++) {
        float x = g_pav[(w * 16 + i) * NN + hv];
        vals[i] = run;
        run += x;
    }
    part[w][lane] = run;

    const bool do2 = (blockIdx.x == 0 && lane < NH);
    float vals2[16];
    float run2 = 0.f;
    if (do2) {
#pragma unroll
        for (int i = 0; i < 16; i++) {
            float x = g_pa[(w * 16 + i) * NH + lane];
            vals2[i] = run2;
            run2 += x;
        }
        part2[w][lane] = run2;
    }
    __syncthreads();

    float off = 0.f, off2 = 0.f;
#pragma unroll
    for (int k = 0; k < 8; k++) {
        if (k < w) {
            off += part[k][lane];
            if (do2) off2 += part2[k][lane];
        }
    }
#pragma unroll
    for (int i = 0; i < 16; i++)
        g_bav[(w * 16 + i) * NN + hv] = off + vals[i];
    if (do2) {
#pragma unroll
        for (int i = 0; i < 16; i++)
            g_basea[(w * 16 + i) * NH + lane] = off2 + vals2[i];
    }
}

// pass3: 32 threads/block, shfl pair-scan of a, __half2 v/attn access.
__global__ void scan_pass3()
{
    const int c = blockIdx.x, h = blockIdx.y, v = threadIdx.x;   // 0..31
    __shared__ float a_s[CH];
    __shared__ float inv_s[CH];
    a_s[v]      = g_a[(c * CH + v) * NH + h];
    a_s[v + 32] = g_a[(c * CH + v + 32) * NH + h];
    __syncwarp();

    float a0 = a_s[2 * v], a1 = a_s[2 * v + 1];
    float p = a0 + a1, sp = p;
#pragma unroll
    for (int off = 1; off < 32; off <<= 1) {
        float n = __shfl_up_sync(0xFFFFFFFFu, sp, off);
        if (v >= off) sp += n;
    }
    float base = g_basea[c * NH + h];
    float excl = base + sp - p;
    inv_s[2 * v]     = 1.0f / (excl + a0);
    inv_s[2 * v + 1] = 1.0f / (excl + a0 + a1);
    __syncwarp();

    const int hv = h * DH + 2 * v;
    const __half2* vp = (const __half2*)(g_v_h + (size_t)c * CH * NN + h * DH) + v;
    __half2* op = (__half2*)(g_attn_h + (size_t)c * CH * NN + h * DH) + v;
    float accx = g_bav[c * NN + hv];
    float accy = g_bav[c * NN + hv + 1];
#pragma unroll 4
    for (int t = 0; t < CH; t++) {
        float2 pv = __half22float2(vp[(size_t)t * (NN / 2)]);
        accx = fmaf(a_s[t], pv.x, accx);
        accy = fmaf(a_s[t], pv.y, accy);
        float inv = inv_s[t];
        op[(size_t)t * (NN / 2)] = __floats2half2_rn(accx * inv, accy * inv);
    }
}

// ---------------------------------------------------------------------------
extern "C" void kernel_launch(void* const* d_in, const int* in_sizes, int n_in,
                              void* d_out, int out_size)
{
    const float* xs = (const float*)d_in[0];
    // d_in[1] = wq: unused (query factor cancels in sq/zq)
    const float* wk = (const float*)d_in[2];
    const float* wv = (const float*)d_in[3];
    const float* w1 = (const float*)d_in[4];
    const float* b1 = (const float*)d_in[5];
    const float* w2 = (const float*)d_in[6];
    const float* b2 = (const float*)d_in[7];
    float* out = (float*)d_out;

    __half *xs_h, *wk_h, *wv_h, *w1_h, *w2_h, *attn_h, *h1_h;
    cudaGetSymbolAddress((void**)&xs_h, g_xs_h);
    cudaGetSymbolAddress((void**)&wk_h, g_wk_h);
    cudaGetSymbolAddress((void**)&wv_h, g_wv_h);
    cudaGetSymbolAddress((void**)&w1_h, g_w1_h);
    cudaGetSymbolAddress((void**)&w2_h, g_w2_h);
    cudaGetSymbolAddress((void**)&attn_h, g_attn_h);
    cudaGetSymbolAddress((void**)&h1_h, g_h1_h);

    cudaFuncSetAttribute(gemm_kv,   cudaFuncAttributeMaxDynamicSharedMemorySize, SMEM_BYTES);
    cudaFuncSetAttribute(gemm_h<2>, cudaFuncAttributeMaxDynamicSharedMemorySize, SMEM_BYTES);
    cudaFuncSetAttribute(gemm_h<3>, cudaFuncAttributeMaxDynamicSharedMemorySize, SMEM_BYTES);

    // 1: conversions (one launch)
    conv_all<<<(12 * 262144) / (256 * 4), 256>>>(
        (const float4*)xs, (__half2*)xs_h,
        (const float4*)wk, (__half2*)wk_h, (const float4*)wv, (__half2*)wv_h,
        (const float4*)w1, (__half2*)w1_h, (const float4*)w2, (__half2*)w2_h);

    // 2: fused k+v projection
    gemm_kv<<<dim3(16, 32), 512, SMEM_BYTES>>>(xs_h, wk_h, wv_h);

    // 3-5: linear-attention chunked scan
    scan_pass1<<<dim3(NC, NH), 32>>>();
    scan_pass2c<<<NN / 32, 256>>>();
    scan_pass3<<<dim3(NC, NH), 32>>>();

    // 6-7: MLP
    gemm_h<2><<<dim3(8, 32), 512, SMEM_BYTES>>>(attn_h, w1_h, b1, h1_h);
    gemm_h<3><<<dim3(8, 32), 512, SMEM_BYTES>>>(h1_h, w2_h, b2, out);
}